// round 9
// baseline (speedup 1.0000x reference)
#include <cuda_runtime.h>
#include <stdint.h>

// Problem constants
#define NB 8
#define NC 512
#define NL 8192
#define NK 3
#define NW (NC*NC*NK)

// Conv tiling
#define TM 64          // C_out per CTA
#define TN 256         // positions per CTA
#define KC 8           // C_in per smem stage
#define NT 256         // threads per CTA (8 warps: 2 M x 4 N)

// Device scratch (allocation-free rule: __device__ globals)
__device__ float  g_wqT[6][NK][NC][NC];     // [widx][tap][ci][co], exact ternary
__device__ float  g_scale[6];
__device__ double g_part[6][96];
__device__ float  g_h[(size_t)NB*NC*NL];    // intermediate h (128 MB)

struct WPtrs { const float* w[6]; };

// ---------------------------------------------------------------------------
// Stage 1: per-slice |w| partial sums, fixed order (deterministic).
__global__ void partial_kernel(WPtrs p) {
    const int widx = blockIdx.y;
    const float* w = p.w[widx] + blockIdx.x * (NW/96);
    __shared__ double sd[256];
    double s = 0.0;
    for (int i = threadIdx.x; i < NW/96; i += 256) s += (double)fabsf(w[i]);
    sd[threadIdx.x] = s;
    __syncthreads();
    for (int o = 128; o > 0; o >>= 1) {
        if (threadIdx.x < o) sd[threadIdx.x] += sd[threadIdx.x + o];
        __syncthreads();
    }
    if (threadIdx.x == 0) g_part[widx][blockIdx.x] = sd[0];
}

// Stage 2: combine partials -> absmean scale per weight tensor.
__global__ void finalize_kernel() {
    const int i = threadIdx.x;
    if (i < 6) {
        double s = 0.0;
        for (int j = 0; j < 96; j++) s += g_part[i][j];
        g_scale[i] = (float)(s / (double)NW) + 1e-5f;
    }
}

// Ternary quantize + transpose to [tap][ci][co] (coalesced writes).
// rintf == jnp.round (half-to-even); __fdiv_rn keeps IEEE div under fast_math.
__global__ void quant_kernel(WPtrs p) {
    const int widx = blockIdx.y;
    const float* __restrict__ w = p.w[widx];
    const float s = g_scale[widx];
    float* __restrict__ dst = &g_wqT[widx][0][0][0];
    for (int o = blockIdx.x*blockDim.x + threadIdx.x; o < NW; o += gridDim.x*blockDim.x) {
        const int co  = o & (NC-1);
        const int r   = o >> 9;
        const int ci  = r & (NC-1);
        const int tap = r >> 9;
        float t = rintf(__fdiv_rn(w[co*(NC*NK) + ci*NK + tap], s));
        dst[o] = fminf(1.0f, fmaxf(-1.0f, t));
    }
}

// ---------------------------------------------------------------------------
__device__ __forceinline__ void mma_tf32(float* d, const uint32_t* a,
                                         uint32_t b0, uint32_t b1) {
    asm volatile(
        "mma.sync.aligned.m16n8k8.row.col.f32.tf32.tf32.f32 "
        "{%0,%1,%2,%3}, {%4,%5,%6,%7}, {%8,%9}, {%0,%1,%2,%3};\n"
        : "+f"(d[0]), "+f"(d[1]), "+f"(d[2]), "+f"(d[3])
        : "r"(a[0]), "r"(a[1]), "r"(a[2]), "r"(a[3]), "r"(b0), "r"(b1));
}

// Fused conv1d (ternary weights) + epilogue, implicit GEMM on tensor cores.
// Double-buffered smem, one __syncthreads per K-chunk, 2 CTAs/SM.
//   MODE 0: out = lrelu(scale*acc + bias)
//   MODE 1: out = res + scale*acc + bias
template<int DIL, int MODE>
__global__ __launch_bounds__(NT, 2)
void conv_kernel(const float* __restrict__ in,
                 const float* __restrict__ res,
                 const float* __restrict__ bias,
                 float* __restrict__ out,
                 int widx)
{
    constexpr int XW = TN + 2*DIL;                // input window incl. halo
    constexpr int XS = (XW <= 264) ? 264 : 296;   // row stride, %32 == 8 (no conflicts)
    constexpr int CS = 72;                        // Wsm co stride, %32 == 8
    constexpr int XN = KC * XW;
    constexpr int WN = NK * KC * TM;              // 1536
    constexpr int XI = (XN + NT - 1) / NT;        // 9
    constexpr int WI = WN / NT;                   // 6
    constexpr int NCH = NC / KC;                  // 64 chunks

    __shared__ uint32_t Xsm[2][KC][XS];           // tf32 bit patterns, double-buffered
    __shared__ float    Wsm[2][NK][KC][CS];       // [tap][ci][co]

    const int t    = threadIdx.x;
    const int lane = t & 31;
    const int wid  = t >> 5;
    const int wm   = wid & 1;                     // warp M index (0..1)
    const int wn   = wid >> 1;                    // warp N index (0..3)
    const int g    = lane >> 2;                   // groupID (0..7)
    const int tg   = lane & 3;                    // thread-in-group (0..3)

    const int co0 = blockIdx.x * TM;
    const int l0  = blockIdx.y * TN;
    const int b   = blockIdx.z;

    const float* __restrict__ wT = &g_wqT[widx][0][0][0];
    const size_t in_b = (size_t)b * NC * NL;

    float acc[2][8][4];
    #pragma unroll
    for (int mi = 0; mi < 2; mi++)
        #pragma unroll
        for (int ni = 0; ni < 8; ni++)
            #pragma unroll
            for (int q = 0; q < 4; q++) acc[mi][ni][q] = 0.0f;

    uint32_t xr[XI];
    float    wr[WI];

    // ---- gmem -> regs for chunk c ----
    auto load_chunk = [&](int c) {
        const int ci0 = c * KC;
        #pragma unroll
        for (int it = 0; it < XI; it++) {
            const int i = t + it*NT;
            uint32_t u = 0u;
            if (i < XN) {
                const int ci = i / XW;
                const int j  = i - ci*XW;
                const int l  = l0 - DIL + j;
                float v = (l >= 0 && l < NL) ? in[in_b + (size_t)(ci0+ci)*NL + l] : 0.0f;
                asm("cvt.rna.tf32.f32 %0, %1;" : "=r"(u) : "f"(v));
            }
            xr[it] = u;
        }
        #pragma unroll
        for (int it = 0; it < WI; it++) {
            const int i   = t + it*NT;
            const int tap = i / (KC*TM);
            const int r   = i - tap*(KC*TM);
            const int ci  = r / TM;
            const int co  = r - ci*TM;
            wr[it] = wT[(size_t)(tap*NC + ci0 + ci)*NC + co0 + co];
        }
    };

    // ---- regs -> smem buffer s ----
    auto store_chunk = [&](int s) {
        #pragma unroll
        for (int it = 0; it < XI; it++) {
            const int i = t + it*NT;
            if (i < XN) { const int ci = i / XW; Xsm[s][ci][i - ci*XW] = xr[it]; }
        }
        #pragma unroll
        for (int it = 0; it < WI; it++) {
            const int i   = t + it*NT;
            const int tap = i / (KC*TM);
            const int r   = i - tap*(KC*TM);
            Wsm[s][tap][r / TM][r % TM] = wr[it];
        }
    };

    const int cwb = wm * 32;
    const int pwb = wn * 64;

    // Prologue: chunk 0 -> buf0, chunk 1 -> regs
    load_chunk(0);
    store_chunk(0);
    load_chunk(1);

    for (int c = 0; c < NCH; c++) {
        __syncthreads();   // buf[c&1] fully written; buf[(c+1)&1] consumers done
        if (c + 1 < NCH) store_chunk((c + 1) & 1);
        if (c + 2 < NCH) load_chunk(c + 2);

        const int s = c & 1;
        #pragma unroll
        for (int tap = 0; tap < NK; tap++) {
            uint32_t a[2][4];
            #pragma unroll
            for (int mi = 0; mi < 2; mi++) {
                const int cw = cwb + mi*16 + g;
                a[mi][0] = __float_as_uint(Wsm[s][tap][tg  ][cw]);
                a[mi][1] = __float_as_uint(Wsm[s][tap][tg  ][cw+8]);
                a[mi][2] = __float_as_uint(Wsm[s][tap][tg+4][cw]);
                a[mi][3] = __float_as_uint(Wsm[s][tap][tg+4][cw+8]);
            }
            #pragma unroll
            for (int ni = 0; ni < 8; ni++) {
                const int col = pwb + ni*8 + g + tap*DIL;
                const uint32_t b0 = Xsm[s][tg  ][col];
                const uint32_t b1 = Xsm[s][tg+4][col];
                mma_tf32(acc[0][ni], a[0], b0, b1);
                mma_tf32(acc[1][ni], a[1], b0, b1);
            }
        }
    }

    // -------- epilogue --------
    const float sc = g_scale[widx];
    #pragma unroll
    for (int mi = 0; mi < 2; mi++) {
        const int co_r = co0 + cwb + mi*16 + g;
        const float bv0 = bias[co_r];
        const float bv1 = bias[co_r + 8];
        #pragma unroll
        for (int ni = 0; ni < 8; ni++) {
            const int pos = l0 + pwb + ni*8 + tg*2;
            const size_t o0 = ((size_t)b*NC + co_r) * NL + pos;
            const size_t o1 = o0 + (size_t)8 * NL;

            float y0 = fmaf(acc[mi][ni][0], sc, bv0);
            float y1 = fmaf(acc[mi][ni][1], sc, bv0);
            float y2 = fmaf(acc[mi][ni][2], sc, bv1);
            float y3 = fmaf(acc[mi][ni][3], sc, bv1);

            float2 v0, v1;
            if (MODE == 0) {
                v0.x = (y0 >= 0.0f) ? y0 : 0.1f*y0;
                v0.y = (y1 >= 0.0f) ? y1 : 0.1f*y1;
                v1.x = (y2 >= 0.0f) ? y2 : 0.1f*y2;
                v1.y = (y3 >= 0.0f) ? y3 : 0.1f*y3;
            } else {
                const float2 r0 = *reinterpret_cast<const float2*>(res + o0);
                const float2 r1 = *reinterpret_cast<const float2*>(res + o1);
                v0.x = y0 + r0.x;  v0.y = y1 + r0.y;
                v1.x = y2 + r1.x;  v1.y = y3 + r1.y;
            }
            *reinterpret_cast<float2*>(out + o0) = v0;
            *reinterpret_cast<float2*>(out + o1) = v1;
        }
    }
}

// ---------------------------------------------------------------------------
extern "C" void kernel_launch(void* const* d_in, const int* in_sizes, int n_in,
                              void* d_out, int out_size)
{
    (void)in_sizes; (void)n_in; (void)out_size;
    const float* x = (const float*)d_in[0];
    WPtrs wp;
    const float* bs[6];
    for (int i = 0; i < 6; i++) {
        wp.w[i] = (const float*)d_in[1 + 2*i];
        bs[i]   = (const float*)d_in[2 + 2*i];
    }
    float* out = (float*)d_out;

    float* h = nullptr;
    cudaGetSymbolAddress((void**)&h, g_h);  // host-side query, capture-safe

    // Weight quantization: parallel deterministic scale + quant/transpose
    partial_kernel<<<dim3(96, 6), 256>>>(wp);
    finalize_kernel<<<1, 32>>>();
    quant_kernel<<<dim3(512, 6), 256>>>(wp);

    dim3 grid(NC/TM, NL/TN, NB);   // (8, 32, 8): co-tiles fastest for L2 reuse

    // Branch 0 (dilation 1):  h = lrelu(conv(x));  out = x + conv(h)
    conv_kernel<1,0><<<grid, NT>>>(x,   nullptr, bs[0], h,   0);
    conv_kernel<1,1><<<grid, NT>>>(h,   x,       bs[1], out, 1);
    // Branch 1 (dilation 3)
    conv_kernel<3,0><<<grid, NT>>>(out, nullptr, bs[2], h,   2);
    conv_kernel<1,1><<<grid, NT>>>(h,   out,     bs[3], out, 3);
    // Branch 2 (dilation 5)
    conv_kernel<5,0><<<grid, NT>>>(out, nullptr, bs[4], h,   4);
    conv_kernel<1,1><<<grid, NT>>>(h,   out,     bs[5], out, 5);
}

// round 17
// speedup vs baseline: 1.8792x; 1.8792x over previous
#include <cuda_runtime.h>
#include <cuda_fp16.h>
#include <stdint.h>

// Problem constants
#define NB 8
#define NC 512
#define NL 8192
#define NK 3
#define NW (NC*NC*NK)

// Conv tiling
#define TM 128         // C_out per CTA
#define TN 256         // positions per CTA
#define KC 16          // C_in per smem stage (8 half2 pairs)
#define NT 512         // threads per CTA (16 warps: 4 M x 4 N)

// Device scratch (allocation-free rule: __device__ globals)
__device__ uint32_t g_wqP[6][NK][NC/2][NC];   // packed half2 ternary: [tap][ci/2][co]
__device__ float    g_scale[6];
__device__ double   g_part[6][96];
__device__ float    g_h[(size_t)NB*NC*NL];    // intermediate h (128 MB)

struct WPtrs { const float* w[6]; };

// ---------------------------------------------------------------------------
// Stage 1: per-slice |w| partial sums, fixed order (deterministic).
__global__ void partial_kernel(WPtrs p) {
    const int widx = blockIdx.y;
    const float* w = p.w[widx] + blockIdx.x * (NW/96);
    __shared__ double sd[256];
    double s = 0.0;
    for (int i = threadIdx.x; i < NW/96; i += 256) s += (double)fabsf(w[i]);
    sd[threadIdx.x] = s;
    __syncthreads();
    for (int o = 128; o > 0; o >>= 1) {
        if (threadIdx.x < o) sd[threadIdx.x] += sd[threadIdx.x + o];
        __syncthreads();
    }
    if (threadIdx.x == 0) g_part[widx][blockIdx.x] = sd[0];
}

// Stage 2: combine partials -> absmean scale per weight tensor.
__global__ void finalize_kernel() {
    const int i = threadIdx.x;
    if (i < 6) {
        double s = 0.0;
        for (int j = 0; j < 96; j++) s += g_part[i][j];
        g_scale[i] = (float)(s / (double)NW) + 1e-5f;
    }
}

// Ternary quantize + transpose + pack pairs of ci into half2 (exact in fp16).
// rintf == jnp.round (half-to-even); __fdiv_rn keeps IEEE div under fast_math.
__global__ void quant_kernel(WPtrs p) {
    const int widx = blockIdx.y;
    const float* __restrict__ w = p.w[widx];
    const float s = g_scale[widx];
    uint32_t* __restrict__ dst = &g_wqP[widx][0][0][0];
    const int NP = NK * (NC/2) * NC;
    for (int o = blockIdx.x*blockDim.x + threadIdx.x; o < NP; o += gridDim.x*blockDim.x) {
        const int co  = o & (NC-1);
        const int r   = o >> 9;          // tap*(NC/2) + cp
        const int cp  = r & (NC/2 - 1);
        const int tap = r >> 8;
        float t0 = rintf(__fdiv_rn(w[co*(NC*NK) + (2*cp  )*NK + tap], s));
        float t1 = rintf(__fdiv_rn(w[co*(NC*NK) + (2*cp+1)*NK + tap], s));
        t0 = fminf(1.0f, fmaxf(-1.0f, t0));
        t1 = fminf(1.0f, fmaxf(-1.0f, t1));
        __half2 h = __floats2half2_rn(t0, t1);   // even ci in low half
        dst[o] = *reinterpret_cast<uint32_t*>(&h);
    }
}

// ---------------------------------------------------------------------------
__device__ __forceinline__ void mma_f16(float* d, const uint32_t* a,
                                        uint32_t b0, uint32_t b1) {
    asm volatile(
        "mma.sync.aligned.m16n8k16.row.col.f32.f16.f16.f32 "
        "{%0,%1,%2,%3}, {%4,%5,%6,%7}, {%8,%9}, {%0,%1,%2,%3};\n"
        : "+f"(d[0]), "+f"(d[1]), "+f"(d[2]), "+f"(d[3])
        : "r"(a[0]), "r"(a[1]), "r"(a[2]), "r"(a[3]), "r"(b0), "r"(b1));
}

// Fused conv1d (ternary weights) + epilogue, implicit GEMM on fp16 tensor cores.
// Double-buffered smem, one __syncthreads per K-chunk (32 chunks of KC=16 ci).
//   MODE 0: out = lrelu(scale*acc + bias)
//   MODE 1: out = res + scale*acc + bias
template<int DIL, int MODE>
__global__ __launch_bounds__(NT, 1)
void conv_kernel(const float* __restrict__ in,
                 const float* __restrict__ res,
                 const float* __restrict__ bias,
                 float* __restrict__ out,
                 int widx)
{
    constexpr int NP  = KC/2;                     // 8 ci-pairs per chunk
    constexpr int XW  = TN + 2*DIL;               // positions incl. halo (words)
    constexpr int XS  = (XW <= 264) ? 264 : 296;  // row stride %32==8 (conflict-free)
    constexpr int CS  = 136;                      // Wsm co stride %32==8
    constexpr int XN  = NP * XW;                  // X words per chunk
    constexpr int WN  = NK * NP * TM;             // 3072 W words per chunk
    constexpr int XI  = (XN + NT - 1) / NT;       // 5
    constexpr int WI  = WN / NT;                  // 6
    constexpr int NCH = NC / KC;                  // 32 chunks

    __shared__ uint32_t Xsm[2][NP][XS];           // half2 (ci even, ci odd) per position
    __shared__ uint32_t Wsm[2][NK][NP][CS];       // half2 (ci even, ci odd) per co

    const int t    = threadIdx.x;
    const int lane = t & 31;
    const int wid  = t >> 5;
    const int wm   = wid & 3;                     // warp M index (0..3)
    const int wn   = wid >> 2;                    // warp N index (0..3)
    const int g    = lane >> 2;                   // groupID (0..7)
    const int tg   = lane & 3;                    // thread-in-group (0..3)

    const int co0 = blockIdx.x * TM;
    const int l0  = blockIdx.y * TN;
    const int b   = blockIdx.z;

    const uint32_t* __restrict__ wP = &g_wqP[widx][0][0][0];
    const size_t in_b = (size_t)b * NC * NL;

    float acc[2][8][4];
    #pragma unroll
    for (int mi = 0; mi < 2; mi++)
        #pragma unroll
        for (int ni = 0; ni < 8; ni++)
            #pragma unroll
            for (int q = 0; q < 4; q++) acc[mi][ni][q] = 0.0f;

    uint32_t xr[XI];
    uint32_t wr[WI];

    // ---- gmem -> regs for chunk c (pack two ci into one half2 word) ----
    auto load_chunk = [&](int c) {
        const int ci0 = c * KC;
        #pragma unroll
        for (int it = 0; it < XI; it++) {
            const int i = t + it*NT;
            uint32_t u = 0u;
            if (i < XN) {
                const int p = i / XW;
                const int j = i - p*XW;
                const int l = l0 - DIL + j;
                float v0 = 0.0f, v1 = 0.0f;
                if (l >= 0 && l < NL) {
                    const float* base = in + in_b + (size_t)(ci0 + 2*p)*NL + l;
                    v0 = base[0];
                    v1 = base[NL];
                }
                __half2 hv = __floats2half2_rn(v0, v1);
                u = *reinterpret_cast<uint32_t*>(&hv);
            }
            xr[it] = u;
        }
        #pragma unroll
        for (int it = 0; it < WI; it++) {
            const int i   = t + it*NT;
            const int tap = i / (NP*TM);
            const int r   = i - tap*(NP*TM);
            const int p   = r >> 7;               // ci-pair 0..7
            const int co  = r & (TM-1);
            wr[it] = wP[(size_t)(tap*(NC/2) + (c*NP + p))*NC + co0 + co];
        }
    };

    // ---- regs -> smem buffer s ----
    auto store_chunk = [&](int s) {
        #pragma unroll
        for (int it = 0; it < XI; it++) {
            const int i = t + it*NT;
            if (i < XN) { const int p = i / XW; Xsm[s][p][i - p*XW] = xr[it]; }
        }
        #pragma unroll
        for (int it = 0; it < WI; it++) {
            const int i   = t + it*NT;
            const int tap = i / (NP*TM);
            const int r   = i - tap*(NP*TM);
            Wsm[s][tap][r >> 7][r & (TM-1)] = wr[it];
        }
    };

    const int cwb = wm * 32;
    const int pwb = wn * 64;

    // Prologue: chunk 0 -> buf0, chunk 1 -> regs
    load_chunk(0);
    store_chunk(0);
    if (NCH > 1) load_chunk(1);

    for (int c = 0; c < NCH; c++) {
        __syncthreads();   // orders: buf[c&1] writes done; prev reads of buf[(c+1)&1] done
        if (c + 1 < NCH) store_chunk((c + 1) & 1);
        if (c + 2 < NCH) load_chunk(c + 2);

        const int s = c & 1;
        #pragma unroll
        for (int tap = 0; tap < NK; tap++) {
            uint32_t a[2][4];
            #pragma unroll
            for (int mi = 0; mi < 2; mi++) {
                const int cw = cwb + mi*16 + g;
                a[mi][0] = Wsm[s][tap][tg  ][cw];     // rows g,   k 2tg..2tg+1
                a[mi][1] = Wsm[s][tap][tg  ][cw+8];   // rows g+8, k 2tg..2tg+1
                a[mi][2] = Wsm[s][tap][tg+4][cw];     // rows g,   k 2tg+8..+9
                a[mi][3] = Wsm[s][tap][tg+4][cw+8];   // rows g+8, k 2tg+8..+9
            }
            #pragma unroll
            for (int ni = 0; ni < 8; ni++) {
                const int col = pwb + ni*8 + g + tap*DIL;
                const uint32_t b0 = Xsm[s][tg  ][col];
                const uint32_t b1 = Xsm[s][tg+4][col];
                mma_f16(acc[0][ni], a[0], b0, b1);
                mma_f16(acc[1][ni], a[1], b0, b1);
            }
        }
    }

    // -------- epilogue --------
    const float sc = g_scale[widx];
    #pragma unroll
    for (int mi = 0; mi < 2; mi++) {
        const int co_r = co0 + cwb + mi*16 + g;
        const float bv0 = bias[co_r];
        const float bv1 = bias[co_r + 8];
        #pragma unroll
        for (int ni = 0; ni < 8; ni++) {
            const int pos = l0 + pwb + ni*8 + tg*2;
            const size_t o0 = ((size_t)b*NC + co_r) * NL + pos;
            const size_t o1 = o0 + (size_t)8 * NL;

            float y0 = fmaf(acc[mi][ni][0], sc, bv0);
            float y1 = fmaf(acc[mi][ni][1], sc, bv0);
            float y2 = fmaf(acc[mi][ni][2], sc, bv1);
            float y3 = fmaf(acc[mi][ni][3], sc, bv1);

            float2 v0, v1;
            if (MODE == 0) {
                v0.x = (y0 >= 0.0f) ? y0 : 0.1f*y0;
                v0.y = (y1 >= 0.0f) ? y1 : 0.1f*y1;
                v1.x = (y2 >= 0.0f) ? y2 : 0.1f*y2;
                v1.y = (y3 >= 0.0f) ? y3 : 0.1f*y3;
            } else {
                const float2 r0 = *reinterpret_cast<const float2*>(res + o0);
                const float2 r1 = *reinterpret_cast<const float2*>(res + o1);
                v0.x = y0 + r0.x;  v0.y = y1 + r0.y;
                v1.x = y2 + r1.x;  v1.y = y3 + r1.y;
            }
            *reinterpret_cast<float2*>(out + o0) = v0;
            *reinterpret_cast<float2*>(out + o1) = v1;
        }
    }
}

// ---------------------------------------------------------------------------
extern "C" void kernel_launch(void* const* d_in, const int* in_sizes, int n_in,
                              void* d_out, int out_size)
{
    (void)in_sizes; (void)n_in; (void)out_size;
    const float* x = (const float*)d_in[0];
    WPtrs wp;
    const float* bs[6];
    for (int i = 0; i < 6; i++) {
        wp.w[i] = (const float*)d_in[1 + 2*i];
        bs[i]   = (const float*)d_in[2 + 2*i];
    }
    float* out = (float*)d_out;

    float* h = nullptr;
    cudaGetSymbolAddress((void**)&h, g_h);  // host-side query, capture-safe

    // Weight quantization: parallel deterministic scale + quant/pack
    partial_kernel<<<dim3(96, 6), 256>>>(wp);
    finalize_kernel<<<1, 32>>>();
    quant_kernel<<<dim3(384, 6), 256>>>(wp);

    dim3 grid(NC/TM, NL/TN, NB);   // (4, 32, 8): co-tiles fastest for L2 reuse

    // Branch 0 (dilation 1):  h = lrelu(conv(x));  out = x + conv(h)
    conv_kernel<1,0><<<grid, NT>>>(x,   nullptr, bs[0], h,   0);
    conv_kernel<1,1><<<grid, NT>>>(h,   x,       bs[1], out, 1);
    // Branch 1 (dilation 3)
    conv_kernel<3,0><<<grid, NT>>>(out, nullptr, bs[2], h,   2);
    conv_kernel<1,1><<<grid, NT>>>(h,   out,     bs[3], out, 3);
    // Branch 2 (dilation 5)
    conv_kernel<5,0><<<grid, NT>>>(out, nullptr, bs[4], h,   4);
    conv_kernel<1,1><<<grid, NT>>>(h,   out,     bs[5], out, 5);
}